// round 11
// baseline (speedup 1.0000x reference)
#include <cuda_runtime.h>
#include <math.h>

#define Bb   2
#define Ss   2048
#define Hh   2048          // HID
#define NHh  16
#define HDd  128
#define NR   (Bb * Ss)     // 4096
#define QN   (3 * NHh * HDd) // 6144

// ---------------- scratch (device globals; zero allocations) ---------------------
__device__ float d_qkv[(size_t)NR * QN];
__device__ float d_qh[(size_t)Bb * NHh * Ss * HDd];   // [B][NH][S][HD]
__device__ float d_kh[(size_t)Bb * NHh * Ss * HDd];
__device__ float d_vh[(size_t)Bb * NHh * Ss * HDd];
__device__ float d_oh[(size_t)NR * Hh];               // [B*S][NH*HD]

// ---------------- tf32 helpers ---------------------------------------------------
__device__ __forceinline__ unsigned f2tf(float f) {
    unsigned u;
    asm("cvt.rna.tf32.f32 %0, %1;" : "=r"(u) : "f"(f));
    return u;
}
__device__ __forceinline__ unsigned b2tf(unsigned bits) {   // rna on raw f32 bits
    unsigned u;
    asm("cvt.rna.tf32.f32 %0, %1;" : "=r"(u) : "f"(__uint_as_float(bits)));
    return u;
}

__device__ __forceinline__ void mma_tf32(float c[4], const unsigned a[4],
                                         const unsigned b[2]) {
    asm volatile(
        "mma.sync.aligned.m16n8k8.row.col.f32.tf32.tf32.f32 "
        "{%0,%1,%2,%3}, {%4,%5,%6,%7}, {%8,%9}, {%0,%1,%2,%3};\n"
        : "+f"(c[0]), "+f"(c[1]), "+f"(c[2]), "+f"(c[3])
        : "r"(a[0]), "r"(a[1]), "r"(a[2]), "r"(a[3]), "r"(b[0]), "r"(b[1]));
}

__device__ __forceinline__ void cp16(unsigned dst, const void* src) {
    asm volatile("cp.async.cg.shared.global [%0], [%1], 16;\n"
                 :: "r"(dst), "l"(src));
}

// ------------- GEMM tc2: C[M,N] = A[M,K] * W[N,K]^T, tf32, cp.async 2-stage ------
// 128x128x32 block, 8 warps, warp tile 64x32. smem holds raw f32 bits;
// cvt.rna.tf32 applied at fragment load (ALU pipe is idle — nearly free).
#define TS 36
#define STG_U (128 * TS)              // one stage of one matrix, in unsigned
#define G_SMEM_BYTES (4 * STG_U * 4)  // sA[2] + sB[2] = 73728 B

__global__ __launch_bounds__(256, 2)
void gemm_tc2(const float* __restrict__ A, const float* __restrict__ W,
              float* __restrict__ C, int M, int N, int K) {
    extern __shared__ __align__(16) unsigned gsm[];
    unsigned* sA[2] = { gsm, gsm + STG_U };
    unsigned* sB[2] = { gsm + 2 * STG_U, gsm + 3 * STG_U };

    const int tid = threadIdx.x;
    const int wid = tid >> 5, lane = tid & 31;
    const int wm = wid & 1, wn = wid >> 1;
    const int lr = lane >> 2, lc = lane & 3;
    const int m0 = blockIdx.y * 128, n0 = blockIdx.x * 128;

    const int glr = tid >> 3;            // 0..31
    const int glc = (tid & 7) << 2;      // 0,4,..,28

    const float* Abase = A + (size_t)m0 * K + glc;
    const float* Wbase = W + (size_t)n0 * K + glc;

    unsigned saA[2][4], saB[2][4];
#pragma unroll
    for (int st = 0; st < 2; st++)
#pragma unroll
        for (int i = 0; i < 4; i++) {
            int row = i * 32 + glr;
            saA[st][i] = (unsigned)__cvta_generic_to_shared(&sA[st][row * TS + glc]);
            saB[st][i] = (unsigned)__cvta_generic_to_shared(&sB[st][row * TS + glc]);
        }

    float acc[4][4][4];
#pragma unroll
    for (int mf = 0; mf < 4; mf++)
#pragma unroll
        for (int nf = 0; nf < 4; nf++)
#pragma unroll
            for (int r = 0; r < 4; r++) acc[mf][nf][r] = 0.0f;

    const int KC = K >> 5;

    // prologue: stage 0
#pragma unroll
    for (int i = 0; i < 4; i++) {
        cp16(saA[0][i], Abase + (size_t)(i * 32 + glr) * K);
        cp16(saB[0][i], Wbase + (size_t)(i * 32 + glr) * K);
    }
    asm volatile("cp.async.commit_group;\n");

    for (int kc = 0; kc < KC; kc++) {
        const int st = kc & 1;
        if (kc + 1 < KC) {
            const int k1 = (kc + 1) << 5;
#pragma unroll
            for (int i = 0; i < 4; i++) {
                cp16(saA[st ^ 1][i], Abase + (size_t)(i * 32 + glr) * K + k1);
                cp16(saB[st ^ 1][i], Wbase + (size_t)(i * 32 + glr) * K + k1);
            }
            asm volatile("cp.async.commit_group;\n");
            asm volatile("cp.async.wait_group 1;\n");
        } else {
            asm volatile("cp.async.wait_group 0;\n");
        }
        __syncthreads();

        const unsigned* cA = sA[st];
        const unsigned* cB = sB[st];
#pragma unroll
        for (int ks = 0; ks < 4; ks++) {
            unsigned af[4][4], bf[4][2];
#pragma unroll
            for (int mf = 0; mf < 4; mf++) {
                int r = wm * 64 + mf * 16 + lr;
                af[mf][0] = b2tf(cA[r * TS + ks * 8 + lc]);
                af[mf][1] = b2tf(cA[(r + 8) * TS + ks * 8 + lc]);
                af[mf][2] = b2tf(cA[r * TS + ks * 8 + lc + 4]);
                af[mf][3] = b2tf(cA[(r + 8) * TS + ks * 8 + lc + 4]);
            }
#pragma unroll
            for (int nf = 0; nf < 4; nf++) {
                int n = wn * 32 + nf * 8 + lr;
                bf[nf][0] = b2tf(cB[n * TS + ks * 8 + lc]);
                bf[nf][1] = b2tf(cB[n * TS + ks * 8 + lc + 4]);
            }
#pragma unroll
            for (int mf = 0; mf < 4; mf++)
#pragma unroll
                for (int nf = 0; nf < 4; nf++)
                    mma_tf32(acc[mf][nf], af[mf], bf[nf]);
        }
        __syncthreads();
    }

#pragma unroll
    for (int mf = 0; mf < 4; mf++)
#pragma unroll
        for (int nf = 0; nf < 4; nf++) {
            int row = m0 + wm * 64 + mf * 16 + lr;
            int col = n0 + wn * 32 + nf * 8 + 2 * lc;
            *(float2*)&C[(size_t)row * N + col] =
                make_float2(acc[mf][nf][0], acc[mf][nf][1]);
            *(float2*)&C[(size_t)(row + 8) * N + col] =
                make_float2(acc[mf][nf][2], acc[mf][nf][3]);
        }
}

// ------------- RMSNorm(flat 2048) + RoPE + scatter  (UNCHANGED — verified) -------
__global__ __launch_bounds__(256)
void rmsrope_v2(const float* __restrict__ qw, const float* __restrict__ kw) {
    const int row = blockIdx.x;
    const int b = row / Ss, s = row - b * Ss;
    const int tid = threadIdx.x;
    const float* base = d_qkv + (size_t)row * QN;

    __shared__ float red[256];
    __shared__ float scl[2];

    float acc = 0.0f;
    for (int i = tid; i < 2048; i += 256) { float v = base[i]; acc += v * v; }
    red[tid] = acc;
    __syncthreads();
    for (int st = 128; st > 0; st >>= 1) {
        if (tid < st) red[tid] += red[tid + st];
        __syncthreads();
    }
    if (tid == 0) scl[0] = 1.0f / sqrtf(red[0] / 2048.0f + 1e-5f);
    __syncthreads();

    acc = 0.0f;
    for (int i = tid; i < 2048; i += 256) { float v = base[2048 + i]; acc += v * v; }
    red[tid] = acc;
    __syncthreads();
    for (int st = 128; st > 0; st >>= 1) {
        if (tid < st) red[tid] += red[tid + st];
        __syncthreads();
    }
    if (tid == 0) scl[1] = 1.0f / sqrtf(red[0] / 2048.0f + 1e-5f);
    __syncthreads();

    const float rq = scl[0], rk = scl[1];

    for (int p = tid; p < NHh * 64; p += 256) {
        int h = p / 64, i = p - h * 64;
        float inv_freq = 1.0f / powf(10000.0f, (float)i / 64.0f);
        float ang = (float)s * inv_freq;
        float cv = cosf(ang), sv = sinf(ang);
        int i1 = h * 128 + i, i2 = i1 + 64;
        float q1 = base[i1] * rq * qw[i1];
        float q2 = base[i2] * rq * qw[i2];
        float k1 = base[2048 + i1] * rk * kw[i1];
        float k2 = base[2048 + i2] * rk * kw[i2];
        size_t o = (((size_t)b * NHh + h) * Ss + s) * HDd;
        d_qh[o + i]      = q1 * cv - q2 * sv;
        d_qh[o + i + 64] = q2 * cv + q1 * sv;
        d_kh[o + i]      = k1 * cv - k2 * sv;
        d_kh[o + i + 64] = k2 * cv + k1 * sv;
    }
    for (int e = tid; e < 2048; e += 256) {
        int h = e / 128, dd = e - h * 128;
        d_vh[(((size_t)b * NHh + h) * Ss + s) * HDd + dd] = base[4096 + e];
    }
}

// ------------- Flash attention tc (tf32 tensor cores, causal) (UNCHANGED) --------
#define KT_STR 72
#define VS_STR 136
#define PS2_STR 68
#define QS_STR 132
#define FK_OFF 0
#define FV_OFF (128 * KT_STR)
#define FP_OFF (FV_OFF + 64 * VS_STR)
#define FT_SMEM_U (FP_OFF + 128 * PS2_STR)
#define FT_SMEM_BYTES (FT_SMEM_U * 4)

__global__ __launch_bounds__(256, 1)
void flash_tc() {
    extern __shared__ __align__(16) unsigned smu[];
    unsigned* KsT = smu + FK_OFF;
    unsigned* Vs  = smu + FV_OFF;
    unsigned* Qst = smu + FK_OFF;
    unsigned* Ps  = smu + FP_OFF;

    const int qb = blockIdx.x, h = blockIdx.y, b = blockIdx.z;
    const int tid = threadIdx.x;
    const int w = tid >> 5, lane = tid & 31;
    const int lr = lane >> 2, lc = lane & 3;
    const size_t head = ((size_t)b * NHh + h) * Ss;
    const float scale = 0.08838834764831845f;

    {
        const float4* Qg = (const float4*)(d_qh + (head + (size_t)qb * 128) * HDd);
        for (int i = tid; i < 128 * 32; i += 256) {
            int r = i >> 5, c = i & 31;
            float4 v = Qg[i];
            Qst[r * QS_STR + 4 * c + 0] = f2tf(v.x * scale);
            Qst[r * QS_STR + 4 * c + 1] = f2tf(v.y * scale);
            Qst[r * QS_STR + 4 * c + 2] = f2tf(v.z * scale);
            Qst[r * QS_STR + 4 * c + 3] = f2tf(v.w * scale);
        }
    }
    __syncthreads();

    unsigned qa[16][4];
#pragma unroll
    for (int ks = 0; ks < 16; ks++) {
        int r0 = (w * 16 + lr) * QS_STR, r1 = (w * 16 + lr + 8) * QS_STR;
        qa[ks][0] = Qst[r0 + ks * 8 + lc];
        qa[ks][1] = Qst[r1 + ks * 8 + lc];
        qa[ks][2] = Qst[r0 + ks * 8 + lc + 4];
        qa[ks][3] = Qst[r1 + ks * 8 + lc + 4];
    }
    __syncthreads();

    float oacc[16][4];
#pragma unroll
    for (int nf = 0; nf < 16; nf++)
#pragma unroll
        for (int r = 0; r < 4; r++) oacc[nf][r] = 0.0f;
    float m_i[2] = {-1e30f, -1e30f}, l_i[2] = {0.0f, 0.0f};

    const int kb_max = 2 * qb + 1;
    for (int kb = 0; kb <= kb_max; kb++) {
        __syncthreads();
        const float4* Kg = (const float4*)(d_kh + (head + (size_t)kb * 64) * HDd);
        const float4* Vg = (const float4*)(d_vh + (head + (size_t)kb * 64) * HDd);
        for (int i = tid; i < 64 * 32; i += 256) {
            int rk = i & 63, ck = (i >> 6) << 2;
            float4 kv = Kg[rk * 32 + (i >> 6)];
            KsT[(ck + 0) * KT_STR + rk] = f2tf(kv.x);
            KsT[(ck + 1) * KT_STR + rk] = f2tf(kv.y);
            KsT[(ck + 2) * KT_STR + rk] = f2tf(kv.z);
            KsT[(ck + 3) * KT_STR + rk] = f2tf(kv.w);
            int rv = i >> 5, cv = i & 31;
            float4 vv = Vg[i];
            Vs[rv * VS_STR + 4 * cv + 0] = f2tf(vv.x);
            Vs[rv * VS_STR + 4 * cv + 1] = f2tf(vv.y);
            Vs[rv * VS_STR + 4 * cv + 2] = f2tf(vv.z);
            Vs[rv * VS_STR + 4 * cv + 3] = f2tf(vv.w);
        }
        __syncthreads();

        float sacc[8][4];
#pragma unroll
        for (int nf = 0; nf < 8; nf++)
#pragma unroll
            for (int r = 0; r < 4; r++) sacc[nf][r] = 0.0f;

#pragma unroll
        for (int ks = 0; ks < 16; ks++) {
            unsigned bf[8][2];
#pragma unroll
            for (int nf = 0; nf < 8; nf++) {
                bf[nf][0] = KsT[(ks * 8 + lc) * KT_STR + nf * 8 + lr];
                bf[nf][1] = KsT[(ks * 8 + lc + 4) * KT_STR + nf * 8 + lr];
            }
#pragma unroll
            for (int nf = 0; nf < 8; nf++)
                mma_tf32(sacc[nf], qa[ks], bf[nf]);
        }

        if (kb >= 2 * qb) {
            int row0 = qb * 128 + w * 16 + lr;
            int row1 = row0 + 8;
#pragma unroll
            for (int nf = 0; nf < 8; nf++) {
                int col = kb * 64 + nf * 8 + 2 * lc;
                if (col > row0)     sacc[nf][0] = -1e30f;
                if (col + 1 > row0) sacc[nf][1] = -1e30f;
                if (col > row1)     sacc[nf][2] = -1e30f;
                if (col + 1 > row1) sacc[nf][3] = -1e30f;
            }
        }

        float mx0 = -1e30f, mx1 = -1e30f;
#pragma unroll
        for (int nf = 0; nf < 8; nf++) {
            mx0 = fmaxf(mx0, fmaxf(sacc[nf][0], sacc[nf][1]));
            mx1 = fmaxf(mx1, fmaxf(sacc[nf][2], sacc[nf][3]));
        }
        mx0 = fmaxf(mx0, __shfl_xor_sync(0xffffffffu, mx0, 1));
        mx0 = fmaxf(mx0, __shfl_xor_sync(0xffffffffu, mx0, 2));
        mx1 = fmaxf(mx1, __shfl_xor_sync(0xffffffffu, mx1, 1));
        mx1 = fmaxf(mx1, __shfl_xor_sync(0xffffffffu, mx1, 2));

        float mn0 = fmaxf(m_i[0], mx0), mn1 = fmaxf(m_i[1], mx1);
        float corr0 = __expf(m_i[0] - mn0), corr1 = __expf(m_i[1] - mn1);
        m_i[0] = mn0; m_i[1] = mn1;

        float rs0 = 0.0f, rs1 = 0.0f;
        unsigned prow0 = (w * 16 + lr) * PS2_STR;
        unsigned prow1 = (w * 16 + lr + 8) * PS2_STR;
#pragma unroll
        for (int nf = 0; nf < 8; nf++) {
            float p0 = __expf(sacc[nf][0] - mn0);
            float p1 = __expf(sacc[nf][1] - mn0);
            float p2 = __expf(sacc[nf][2] - mn1);
            float p3 = __expf(sacc[nf][3] - mn1);
            rs0 += p0 + p1; rs1 += p2 + p3;
            *(uint2*)&Ps[prow0 + nf * 8 + 2 * lc] = make_uint2(f2tf(p0), f2tf(p1));
            *(uint2*)&Ps[prow1 + nf * 8 + 2 * lc] = make_uint2(f2tf(p2), f2tf(p3));
        }
        rs0 += __shfl_xor_sync(0xffffffffu, rs0, 1);
        rs0 += __shfl_xor_sync(0xffffffffu, rs0, 2);
        rs1 += __shfl_xor_sync(0xffffffffu, rs1, 1);
        rs1 += __shfl_xor_sync(0xffffffffu, rs1, 2);
        l_i[0] = l_i[0] * corr0 + rs0;
        l_i[1] = l_i[1] * corr1 + rs1;

#pragma unroll
        for (int nf = 0; nf < 16; nf++) {
            oacc[nf][0] *= corr0; oacc[nf][1] *= corr0;
            oacc[nf][2] *= corr1; oacc[nf][3] *= corr1;
        }
        __syncwarp();

#pragma unroll
        for (int ks = 0; ks < 8; ks++) {
            unsigned pa[4];
            pa[0] = Ps[prow0 + ks * 8 + lc];
            pa[1] = Ps[prow1 + ks * 8 + lc];
            pa[2] = Ps[prow0 + ks * 8 + lc + 4];
            pa[3] = Ps[prow1 + ks * 8 + lc + 4];
#pragma unroll
            for (int nf = 0; nf < 16; nf++) {
                unsigned vb[2];
                vb[0] = Vs[(ks * 8 + lc) * VS_STR + nf * 8 + lr];
                vb[1] = Vs[(ks * 8 + lc + 4) * VS_STR + nf * 8 + lr];
                mma_tf32(oacc[nf], pa, vb);
            }
        }
    }

    float inv0 = 1.0f / l_i[0], inv1 = 1.0f / l_i[1];
    int row0 = qb * 128 + w * 16 + lr;
#pragma unroll
    for (int nf = 0; nf < 16; nf++) {
        int col = h * HDd + nf * 8 + 2 * lc;
        *(float2*)&d_oh[((size_t)b * Ss + row0) * Hh + col] =
            make_float2(oacc[nf][0] * inv0, oacc[nf][1] * inv0);
        *(float2*)&d_oh[((size_t)b * Ss + row0 + 8) * Hh + col] =
            make_float2(oacc[nf][2] * inv1, oacc[nf][3] * inv1);
    }
}

// ---------------- launch ----------------------------------------------------------
extern "C" void kernel_launch(void* const* d_in, const int* in_sizes, int n_in,
                              void* d_out, int out_size) {
    const float* x     = nullptr;
    const float* w_in  = nullptr;
    const float* w_out = nullptr;
    const float* qw    = nullptr;
    const float* kw    = nullptr;

    for (int i = 0; i < n_in; i++) {
        const float* p = (const float*)d_in[i];
        int n = in_sizes[i];
        if      (n == Bb * Ss * Hh)   x = p;
        else if (n == QN * Hh)        w_in = p;
        else if (n == Hh * NHh * HDd) w_out = p;
        else if (n == NHh * HDd) { if (!qw) qw = p; else kw = p; }
    }
    float* out = (float*)d_out;

    float *qkv_p = nullptr, *o_p = nullptr;
    cudaGetSymbolAddress((void**)&qkv_p, d_qkv);
    cudaGetSymbolAddress((void**)&o_p, d_oh);

    cudaFuncSetAttribute(gemm_tc2,
                         cudaFuncAttributeMaxDynamicSharedMemorySize, G_SMEM_BYTES);
    cudaFuncSetAttribute(flash_tc,
                         cudaFuncAttributeMaxDynamicSharedMemorySize, FT_SMEM_BYTES);

    // 1) qkv = x @ w_in^T  (tf32, cp.async pipelined, rna at frag load)
    gemm_tc2<<<dim3(QN / 128, NR / 128), 256, G_SMEM_BYTES>>>(x, w_in, qkv_p, NR, QN, Hh);

    // 2) rmsnorm(q,k) + rope + scatter
    rmsrope_v2<<<NR, 256>>>(qw, kw);

    // 3) causal flash attention (tf32 tensor cores)
    flash_tc<<<dim3(Ss / 128, NHh, Bb), 256, FT_SMEM_BYTES>>>();

    // 4) out = O @ w_out^T  (tf32, cp.async pipelined, rna at frag load)
    gemm_tc2<<<dim3(Hh / 128, NR / 128), 256, G_SMEM_BYTES>>>(o_p, w_out, out, NR, Hh, NHh * HDd);
}

// round 13
// speedup vs baseline: 1.0990x; 1.0990x over previous
#include <cuda_runtime.h>
#include <math.h>

#define Bb   2
#define Ss   2048
#define Hh   2048          // HID
#define NHh  16
#define HDd  128
#define NR   (Bb * Ss)     // 4096
#define QN   (3 * NHh * HDd) // 6144

// ---------------- scratch (device globals; zero allocations) ---------------------
__device__ float    d_qkv[(size_t)NR * QN];             // GEMM1 out; later: tf32(oh)
__device__ unsigned d_qh[(size_t)Bb * NHh * Ss * HDd];  // tf32 bits, pre-scaled
__device__ unsigned d_kh[(size_t)Bb * NHh * Ss * HDd];  // tf32 bits
__device__ unsigned d_vh[(size_t)Bb * NHh * Ss * HDd];  // tf32 bits
__device__ float    d_oh[(size_t)NR * Hh];              // flash out (f32)
__device__ unsigned d_xt[(size_t)NR * Hh];              // tf32(x)
__device__ unsigned d_wint[(size_t)QN * Hh];            // tf32(w_in)
__device__ unsigned d_wot[(size_t)Hh * NHh * HDd];      // tf32(w_out)

// ---------------- tf32 helpers ---------------------------------------------------
__device__ __forceinline__ unsigned f2tf(float f) {
    unsigned u;
    asm("cvt.rna.tf32.f32 %0, %1;" : "=r"(u) : "f"(f));
    return u;
}

__device__ __forceinline__ void mma_tf32(float c[4], const unsigned a[4],
                                         const unsigned b[2]) {
    asm volatile(
        "mma.sync.aligned.m16n8k8.row.col.f32.tf32.tf32.f32 "
        "{%0,%1,%2,%3}, {%4,%5,%6,%7}, {%8,%9}, {%0,%1,%2,%3};\n"
        : "+f"(c[0]), "+f"(c[1]), "+f"(c[2]), "+f"(c[3])
        : "r"(a[0]), "r"(a[1]), "r"(a[2]), "r"(a[3]), "r"(b[0]), "r"(b[1]));
}

__device__ __forceinline__ void cp16(unsigned dst, const void* src) {
    asm volatile("cp.async.cg.shared.global [%0], [%1], 16;\n"
                 :: "r"(dst), "l"(src));
}

// ------------- elementwise f32 -> tf32-bits conversion ---------------------------
__global__ __launch_bounds__(256)
void cvt_tf32(const float* __restrict__ src, unsigned* __restrict__ dst) {
    int i = (blockIdx.x * 256 + threadIdx.x) * 4;
    float4 v = *(const float4*)(src + i);
    *(uint4*)(dst + i) = make_uint4(f2tf(v.x), f2tf(v.y), f2tf(v.z), f2tf(v.w));
}

// ------------- GEMM tc2: C[M,N] = A[M,K] * W[N,K]^T, pre-converted tf32 ----------
// 128x128x32 block, 8 warps, warp tile 64x32, cp.async 2-stage; zero cvt in loop.
#define TS 36
#define STG_U (128 * TS)
#define G_SMEM_BYTES (4 * STG_U * 4)  // 73728 B

__global__ __launch_bounds__(256, 2)
void gemm_tc2(const unsigned* __restrict__ A, const unsigned* __restrict__ W,
              float* __restrict__ C, int M, int N, int K) {
    extern __shared__ __align__(16) unsigned gsm[];
    unsigned* sA[2] = { gsm, gsm + STG_U };
    unsigned* sB[2] = { gsm + 2 * STG_U, gsm + 3 * STG_U };

    const int tid = threadIdx.x;
    const int wid = tid >> 5, lane = tid & 31;
    const int wm = wid & 1, wn = wid >> 1;
    const int lr = lane >> 2, lc = lane & 3;
    const int m0 = blockIdx.y * 128, n0 = blockIdx.x * 128;

    const int glr = tid >> 3;
    const int glc = (tid & 7) << 2;

    const unsigned* Abase = A + (size_t)m0 * K + glc;
    const unsigned* Wbase = W + (size_t)n0 * K + glc;

    unsigned saA[2][4], saB[2][4];
#pragma unroll
    for (int st = 0; st < 2; st++)
#pragma unroll
        for (int i = 0; i < 4; i++) {
            int row = i * 32 + glr;
            saA[st][i] = (unsigned)__cvta_generic_to_shared(&sA[st][row * TS + glc]);
            saB[st][i] = (unsigned)__cvta_generic_to_shared(&sB[st][row * TS + glc]);
        }

    float acc[4][4][4];
#pragma unroll
    for (int mf = 0; mf < 4; mf++)
#pragma unroll
        for (int nf = 0; nf < 4; nf++)
#pragma unroll
            for (int r = 0; r < 4; r++) acc[mf][nf][r] = 0.0f;

    const int KC = K >> 5;

#pragma unroll
    for (int i = 0; i < 4; i++) {
        cp16(saA[0][i], Abase + (size_t)(i * 32 + glr) * K);
        cp16(saB[0][i], Wbase + (size_t)(i * 32 + glr) * K);
    }
    asm volatile("cp.async.commit_group;\n");

    for (int kc = 0; kc < KC; kc++) {
        const int st = kc & 1;
        if (kc + 1 < KC) {
            const int k1 = (kc + 1) << 5;
#pragma unroll
            for (int i = 0; i < 4; i++) {
                cp16(saA[st ^ 1][i], Abase + (size_t)(i * 32 + glr) * K + k1);
                cp16(saB[st ^ 1][i], Wbase + (size_t)(i * 32 + glr) * K + k1);
            }
            asm volatile("cp.async.commit_group;\n");
            asm volatile("cp.async.wait_group 1;\n");
        } else {
            asm volatile("cp.async.wait_group 0;\n");
        }
        __syncthreads();

        const unsigned* cA = sA[st];
        const unsigned* cB = sB[st];
#pragma unroll
        for (int ks = 0; ks < 4; ks++) {
            unsigned af[4][4], bf[4][2];
#pragma unroll
            for (int mf = 0; mf < 4; mf++) {
                int r = wm * 64 + mf * 16 + lr;
                af[mf][0] = cA[r * TS + ks * 8 + lc];
                af[mf][1] = cA[(r + 8) * TS + ks * 8 + lc];
                af[mf][2] = cA[r * TS + ks * 8 + lc + 4];
                af[mf][3] = cA[(r + 8) * TS + ks * 8 + lc + 4];
            }
#pragma unroll
            for (int nf = 0; nf < 4; nf++) {
                int n = wn * 32 + nf * 8 + lr;
                bf[nf][0] = cB[n * TS + ks * 8 + lc];
                bf[nf][1] = cB[n * TS + ks * 8 + lc + 4];
            }
#pragma unroll
            for (int mf = 0; mf < 4; mf++)
#pragma unroll
                for (int nf = 0; nf < 4; nf++)
                    mma_tf32(acc[mf][nf], af[mf], bf[nf]);
        }
        __syncthreads();
    }

#pragma unroll
    for (int mf = 0; mf < 4; mf++)
#pragma unroll
        for (int nf = 0; nf < 4; nf++) {
            int row = m0 + wm * 64 + mf * 16 + lr;
            int col = n0 + wn * 32 + nf * 8 + 2 * lc;
            *(float2*)&C[(size_t)row * N + col] =
                make_float2(acc[mf][nf][0], acc[mf][nf][1]);
            *(float2*)&C[(size_t)(row + 8) * N + col] =
                make_float2(acc[mf][nf][2], acc[mf][nf][3]);
        }
}

// ------------- RMSNorm + RoPE + scatter; emits tf32 bits (q pre-scaled) ----------
__global__ __launch_bounds__(256)
void rmsrope_v3(const float* __restrict__ qw, const float* __restrict__ kw) {
    const int row = blockIdx.x;
    const int b = row / Ss, s = row - b * Ss;
    const int tid = threadIdx.x;
    const float* base = d_qkv + (size_t)row * QN;

    __shared__ float red[256];
    __shared__ float scl[2];

    float acc = 0.0f;
    for (int i = tid; i < 2048; i += 256) { float v = base[i]; acc += v * v; }
    red[tid] = acc;
    __syncthreads();
    for (int st = 128; st > 0; st >>= 1) {
        if (tid < st) red[tid] += red[tid + st];
        __syncthreads();
    }
    if (tid == 0) scl[0] = 1.0f / sqrtf(red[0] / 2048.0f + 1e-5f);
    __syncthreads();

    acc = 0.0f;
    for (int i = tid; i < 2048; i += 256) { float v = base[2048 + i]; acc += v * v; }
    red[tid] = acc;
    __syncthreads();
    for (int st = 128; st > 0; st >>= 1) {
        if (tid < st) red[tid] += red[tid + st];
        __syncthreads();
    }
    if (tid == 0) scl[1] = 1.0f / sqrtf(red[0] / 2048.0f + 1e-5f);
    __syncthreads();

    const float rq = scl[0], rk = scl[1];
    const float atts = 0.08838834764831845f;   // 1/sqrt(128)

    for (int p = tid; p < NHh * 64; p += 256) {
        int h = p / 64, i = p - h * 64;
        float inv_freq = 1.0f / powf(10000.0f, (float)i / 64.0f);
        float ang = (float)s * inv_freq;
        float cv = cosf(ang), sv = sinf(ang);
        int i1 = h * 128 + i, i2 = i1 + 64;
        float q1 = base[i1] * rq * qw[i1];
        float q2 = base[i2] * rq * qw[i2];
        float k1 = base[2048 + i1] * rk * kw[i1];
        float k2 = base[2048 + i2] * rk * kw[i2];
        size_t o = (((size_t)b * NHh + h) * Ss + s) * HDd;
        d_qh[o + i]      = f2tf((q1 * cv - q2 * sv) * atts);
        d_qh[o + i + 64] = f2tf((q2 * cv + q1 * sv) * atts);
        d_kh[o + i]      = f2tf(k1 * cv - k2 * sv);
        d_kh[o + i + 64] = f2tf(k2 * cv + k1 * sv);
    }
    for (int e = tid; e < 2048; e += 256) {
        int h = e / 128, dd = e - h * 128;
        d_vh[(((size_t)b * NHh + h) * Ss + s) * HDd + dd] = f2tf(base[4096 + e]);
    }
}

// ------------- Flash attention tc (tf32; operands pre-converted) -----------------
#define KT_STR 72
#define VS_STR 136
#define PS2_STR 68
#define QS_STR 132
#define FK_OFF 0
#define FV_OFF (128 * KT_STR)
#define FP_OFF (FV_OFF + 64 * VS_STR)
#define FT_SMEM_U (FP_OFF + 128 * PS2_STR)
#define FT_SMEM_BYTES (FT_SMEM_U * 4)

__global__ __launch_bounds__(256, 1)
void flash_tc() {
    extern __shared__ __align__(16) unsigned smu[];
    unsigned* KsT = smu + FK_OFF;
    unsigned* Vs  = smu + FV_OFF;
    unsigned* Qst = smu + FK_OFF;
    unsigned* Ps  = smu + FP_OFF;

    const int qb = blockIdx.x, h = blockIdx.y, b = blockIdx.z;
    const int tid = threadIdx.x;
    const int w = tid >> 5, lane = tid & 31;
    const int lr = lane >> 2, lc = lane & 3;
    const size_t head = ((size_t)b * NHh + h) * Ss;

    {
        const uint4* Qg = (const uint4*)(d_qh + (head + (size_t)qb * 128) * HDd);
        for (int i = tid; i < 128 * 32; i += 256) {
            int r = i >> 5, c = i & 31;
            uint4 v = Qg[i];
            Qst[r * QS_STR + 4 * c + 0] = v.x;
            Qst[r * QS_STR + 4 * c + 1] = v.y;
            Qst[r * QS_STR + 4 * c + 2] = v.z;
            Qst[r * QS_STR + 4 * c + 3] = v.w;
        }
    }
    __syncthreads();

    unsigned qa[16][4];
#pragma unroll
    for (int ks = 0; ks < 16; ks++) {
        int r0 = (w * 16 + lr) * QS_STR, r1 = (w * 16 + lr + 8) * QS_STR;
        qa[ks][0] = Qst[r0 + ks * 8 + lc];
        qa[ks][1] = Qst[r1 + ks * 8 + lc];
        qa[ks][2] = Qst[r0 + ks * 8 + lc + 4];
        qa[ks][3] = Qst[r1 + ks * 8 + lc + 4];
    }
    __syncthreads();

    float oacc[16][4];
#pragma unroll
    for (int nf = 0; nf < 16; nf++)
#pragma unroll
        for (int r = 0; r < 4; r++) oacc[nf][r] = 0.0f;
    float m_i[2] = {-1e30f, -1e30f}, l_i[2] = {0.0f, 0.0f};

    const int kb_max = 2 * qb + 1;
    for (int kb = 0; kb <= kb_max; kb++) {
        __syncthreads();
        const uint4* Kg = (const uint4*)(d_kh + (head + (size_t)kb * 64) * HDd);
        const uint4* Vg = (const uint4*)(d_vh + (head + (size_t)kb * 64) * HDd);
        for (int i = tid; i < 64 * 32; i += 256) {
            int rk = i & 63, ck = (i >> 6) << 2;
            uint4 kv = Kg[rk * 32 + (i >> 6)];
            KsT[(ck + 0) * KT_STR + rk] = kv.x;
            KsT[(ck + 1) * KT_STR + rk] = kv.y;
            KsT[(ck + 2) * KT_STR + rk] = kv.z;
            KsT[(ck + 3) * KT_STR + rk] = kv.w;
            int rv = i >> 5, cv = i & 31;
            uint4 vv = Vg[i];
            Vs[rv * VS_STR + 4 * cv + 0] = vv.x;
            Vs[rv * VS_STR + 4 * cv + 1] = vv.y;
            Vs[rv * VS_STR + 4 * cv + 2] = vv.z;
            Vs[rv * VS_STR + 4 * cv + 3] = vv.w;
        }
        __syncthreads();

        float sacc[8][4];
#pragma unroll
        for (int nf = 0; nf < 8; nf++)
#pragma unroll
            for (int r = 0; r < 4; r++) sacc[nf][r] = 0.0f;

#pragma unroll
        for (int ks = 0; ks < 16; ks++) {
            unsigned bf[8][2];
#pragma unroll
            for (int nf = 0; nf < 8; nf++) {
                bf[nf][0] = KsT[(ks * 8 + lc) * KT_STR + nf * 8 + lr];
                bf[nf][1] = KsT[(ks * 8 + lc + 4) * KT_STR + nf * 8 + lr];
            }
#pragma unroll
            for (int nf = 0; nf < 8; nf++)
                mma_tf32(sacc[nf], qa[ks], bf[nf]);
        }

        if (kb >= 2 * qb) {
            int row0 = qb * 128 + w * 16 + lr;
            int row1 = row0 + 8;
#pragma unroll
            for (int nf = 0; nf < 8; nf++) {
                int col = kb * 64 + nf * 8 + 2 * lc;
                if (col > row0)     sacc[nf][0] = -1e30f;
                if (col + 1 > row0) sacc[nf][1] = -1e30f;
                if (col > row1)     sacc[nf][2] = -1e30f;
                if (col + 1 > row1) sacc[nf][3] = -1e30f;
            }
        }

        float mx0 = -1e30f, mx1 = -1e30f;
#pragma unroll
        for (int nf = 0; nf < 8; nf++) {
            mx0 = fmaxf(mx0, fmaxf(sacc[nf][0], sacc[nf][1]));
            mx1 = fmaxf(mx1, fmaxf(sacc[nf][2], sacc[nf][3]));
        }
        mx0 = fmaxf(mx0, __shfl_xor_sync(0xffffffffu, mx0, 1));
        mx0 = fmaxf(mx0, __shfl_xor_sync(0xffffffffu, mx0, 2));
        mx1 = fmaxf(mx1, __shfl_xor_sync(0xffffffffu, mx1, 1));
        mx1 = fmaxf(mx1, __shfl_xor_sync(0xffffffffu, mx1, 2));

        float mn0 = fmaxf(m_i[0], mx0), mn1 = fmaxf(m_i[1], mx1);
        float corr0 = __expf(m_i[0] - mn0), corr1 = __expf(m_i[1] - mn1);
        m_i[0] = mn0; m_i[1] = mn1;

        float rs0 = 0.0f, rs1 = 0.0f;
        unsigned prow0 = (w * 16 + lr) * PS2_STR;
        unsigned prow1 = (w * 16 + lr + 8) * PS2_STR;
#pragma unroll
        for (int nf = 0; nf < 8; nf++) {
            float p0 = __expf(sacc[nf][0] - mn0);
            float p1 = __expf(sacc[nf][1] - mn0);
            float p2 = __expf(sacc[nf][2] - mn1);
            float p3 = __expf(sacc[nf][3] - mn1);
            rs0 += p0 + p1; rs1 += p2 + p3;
            *(uint2*)&Ps[prow0 + nf * 8 + 2 * lc] = make_uint2(f2tf(p0), f2tf(p1));
            *(uint2*)&Ps[prow1 + nf * 8 + 2 * lc] = make_uint2(f2tf(p2), f2tf(p3));
        }
        rs0 += __shfl_xor_sync(0xffffffffu, rs0, 1);
        rs0 += __shfl_xor_sync(0xffffffffu, rs0, 2);
        rs1 += __shfl_xor_sync(0xffffffffu, rs1, 1);
        rs1 += __shfl_xor_sync(0xffffffffu, rs1, 2);
        l_i[0] = l_i[0] * corr0 + rs0;
        l_i[1] = l_i[1] * corr1 + rs1;

#pragma unroll
        for (int nf = 0; nf < 16; nf++) {
            oacc[nf][0] *= corr0; oacc[nf][1] *= corr0;
            oacc[nf][2] *= corr1; oacc[nf][3] *= corr1;
        }
        __syncwarp();

#pragma unroll
        for (int ks = 0; ks < 8; ks++) {
            unsigned pa[4];
            pa[0] = Ps[prow0 + ks * 8 + lc];
            pa[1] = Ps[prow1 + ks * 8 + lc];
            pa[2] = Ps[prow0 + ks * 8 + lc + 4];
            pa[3] = Ps[prow1 + ks * 8 + lc + 4];
#pragma unroll
            for (int nf = 0; nf < 16; nf++) {
                unsigned vb[2];
                vb[0] = Vs[(ks * 8 + lc) * VS_STR + nf * 8 + lr];
                vb[1] = Vs[(ks * 8 + lc + 4) * VS_STR + nf * 8 + lr];
                mma_tf32(oacc[nf], pa, vb);
            }
        }
    }

    float inv0 = 1.0f / l_i[0], inv1 = 1.0f / l_i[1];
    int row0 = qb * 128 + w * 16 + lr;
#pragma unroll
    for (int nf = 0; nf < 16; nf++) {
        int col = h * HDd + nf * 8 + 2 * lc;
        *(float2*)&d_oh[((size_t)b * Ss + row0) * Hh + col] =
            make_float2(oacc[nf][0] * inv0, oacc[nf][1] * inv0);
        *(float2*)&d_oh[((size_t)b * Ss + row0 + 8) * Hh + col] =
            make_float2(oacc[nf][2] * inv1, oacc[nf][3] * inv1);
    }
}

// ---------------- launch ----------------------------------------------------------
extern "C" void kernel_launch(void* const* d_in, const int* in_sizes, int n_in,
                              void* d_out, int out_size) {
    const float* x     = nullptr;
    const float* w_in  = nullptr;
    const float* w_out = nullptr;
    const float* qw    = nullptr;
    const float* kw    = nullptr;

    for (int i = 0; i < n_in; i++) {
        const float* p = (const float*)d_in[i];
        int n = in_sizes[i];
        if      (n == Bb * Ss * Hh)   x = p;
        else if (n == QN * Hh)        w_in = p;
        else if (n == Hh * NHh * HDd) w_out = p;
        else if (n == NHh * HDd) { if (!qw) qw = p; else kw = p; }
    }
    float* out = (float*)d_out;

    float* qkv_p = nullptr; float* oh_p = nullptr;
    unsigned *xt_p = nullptr, *wint_p = nullptr, *wot_p = nullptr;
    cudaGetSymbolAddress((void**)&qkv_p, d_qkv);
    cudaGetSymbolAddress((void**)&oh_p, d_oh);
    cudaGetSymbolAddress((void**)&xt_p, d_xt);
    cudaGetSymbolAddress((void**)&wint_p, d_wint);
    cudaGetSymbolAddress((void**)&wot_p, d_wot);

    cudaFuncSetAttribute(gemm_tc2,
                         cudaFuncAttributeMaxDynamicSharedMemorySize, G_SMEM_BYTES);
    cudaFuncSetAttribute(flash_tc,
                         cudaFuncAttributeMaxDynamicSharedMemorySize, FT_SMEM_BYTES);

    // 0) pre-convert operands to tf32 bits
    cvt_tf32<<<(NR * Hh) / 1024, 256>>>(x, xt_p);
    cvt_tf32<<<(QN * Hh) / 1024, 256>>>(w_in, wint_p);
    cvt_tf32<<<(Hh * NHh * HDd) / 1024, 256>>>(w_out, wot_p);

    // 1) qkv = x @ w_in^T
    gemm_tc2<<<dim3(QN / 128, NR / 128), 256, G_SMEM_BYTES>>>(xt_p, wint_p, qkv_p, NR, QN, Hh);

    // 2) rmsnorm(q,k) + rope + scatter (emits tf32 bits, q pre-scaled)
    rmsrope_v3<<<NR, 256>>>(qw, kw);

    // 3) causal flash attention
    flash_tc<<<dim3(Ss / 128, NHh, Bb), 256, FT_SMEM_BYTES>>>();

    // 3b) convert flash output to tf32 bits (reuse d_qkv scratch)
    cvt_tf32<<<(NR * Hh) / 1024, 256>>>(oh_p, (unsigned*)qkv_p);

    // 4) out = O @ w_out^T
    gemm_tc2<<<dim3(Hh / 128, NR / 128), 256, G_SMEM_BYTES>>>((unsigned*)qkv_p, wot_p, out, NR, Hh, NHh * HDd);
}